// round 8
// baseline (speedup 1.0000x reference)
#include <cuda_runtime.h>
#include <cuda_bf16.h>
#include <math.h>
#include <stdint.h>

#define DTC 0.001
#define Pdim 1024
#define Hdim 256
#define Ldim 16384
#define NKC  16             // K chunks of 64 (K = 1024 per GEMM)
#define STAGE_BYTES 98304   // Ahi 16K | Alo 16K | Bhi 32K | Blo 32K

// ---------------------------------------------------------------------------
// Device-global scratch (allocation-free rule)
// ---------------------------------------------------------------------------
__device__ __align__(16) float2  g_ab[Pdim];     // fp32 A_bar
__device__ __align__(16) float2  g_cf[Pdim];     // (A_bar-1)/Ac
__device__ __align__(16) double2 g_lg[Pdim];     // log(A_bar) fp64
// A planes [variant: r_hi, r_lo, i_hi, i_lo, s_hi, s_lo][kc(16)][m=h(256)][kk(64)]
__device__ __align__(128) __nv_bfloat16 g_A[6][(size_t)16 * 256 * 64];
// B planes same variant order, [kc(16)][n=l(16384)][kk(64)]  (32 MB each)
__device__ __align__(128) __nv_bfloat16 g_B[6][(size_t)16 * 16384 * 64];
// Partial GEMM outputs Gr, Gi, Gm  (16 MB each)
__device__ __align__(128) float g_G[3][(size_t)256 * 16384];

// ---------------------------------------------------------------------------
// helpers
// ---------------------------------------------------------------------------
__device__ __forceinline__ uint32_t s2u(const void* p) {
    uint32_t a;
    asm("{ .reg .u64 t; cvta.to.shared.u64 t, %1; cvt.u32.u64 %0, t; }"
        : "=r"(a) : "l"(p));
    return a;
}

__device__ __forceinline__ void cpa(uint32_t dst, const void* src) {
    asm volatile("cp.async.cg.shared.global [%0], [%1], 16;"
                 :: "r"(dst), "l"(src) : "memory");
}

__device__ __forceinline__ void ldm4(uint32_t* r, uint32_t a) {
    asm volatile("ldmatrix.sync.aligned.m8n8.x4.shared.b16 {%0,%1,%2,%3}, [%4];"
                 : "=r"(r[0]), "=r"(r[1]), "=r"(r[2]), "=r"(r[3]) : "r"(a));
}

__device__ __forceinline__ void mma16816(float* d, const uint32_t* a,
                                         uint32_t b0, uint32_t b1) {
    asm volatile(
        "mma.sync.aligned.m16n8k16.row.col.f32.bf16.bf16.f32 "
        "{%0,%1,%2,%3}, {%4,%5,%6,%7}, {%8,%9}, {%0,%1,%2,%3};"
        : "+f"(d[0]), "+f"(d[1]), "+f"(d[2]), "+f"(d[3])
        : "r"(a[0]), "r"(a[1]), "r"(a[2]), "r"(a[3]), "r"(b0), "r"(b1));
}

// ---------------------------------------------------------------------------
// k_pre: per-p constants (fp64 transcendentals once per p)
// ---------------------------------------------------------------------------
__global__ void k_pre(const float* __restrict__ A) {
    int p = blockIdx.x * blockDim.x + threadIdx.x;
    if (p >= Pdim) return;
    float ar = A[2 * p], ai = A[2 * p + 1];
    double e = exp((double)ar * DTC), th = (double)ai * DTC;
    float abr = (float)(e * cos(th));
    float abi = (float)(e * sin(th));
    float nr = abr - 1.0f, ni = abi;
    float den = ar * ar + ai * ai;
    g_ab[p] = make_float2(abr, abi);
    g_cf[p] = make_float2((nr * ar + ni * ai) / den, (ni * ar - nr * ai) / den);
    g_lg[p] = make_double2(0.5 * log((double)abr * abr + (double)abi * abi),
                           atan2((double)abi, (double)abr));
}

// ---------------------------------------------------------------------------
// k_fill: merged B-generation (blocks 0..511) + A-setup (blocks 512..1535)
// so the small setupA work rides along concurrently.
// ---------------------------------------------------------------------------
__global__ void k_fill(const float* __restrict__ B, const float* __restrict__ C) {
    if (blockIdx.x < 512) {
        // ---- genB: V[p,l] fp32 recurrence, fp64 seed every 128 l ----
        int wid = blockIdx.x * 8 + (threadIdx.x >> 5);   // 4096 warps
        int lane = threadIdx.x & 31;
        int pg = wid & 31, seg = wid >> 5;               // seg 0..127
        int p = pg * 32 + lane;

        float2 ab = g_ab[p];
        double2 lg = g_lg[p];
        int l0 = seg * 128;
        double m = exp(lg.x * (double)l0), a = lg.y * (double)l0;
        float vr = (float)(m * cos(a));
        float vi = (float)(m * sin(a));

        const size_t kcbase = (size_t)(p >> 6) * 16384;
        const int kk = p & 63;

        #pragma unroll 4
        for (int t = 0; t < 128; t++) {
            int l = l0 + t;
            float vs = vr + vi;
            __nv_bfloat16 hr = __float2bfloat16_rn(vr);
            __nv_bfloat16 hi = __float2bfloat16_rn(vi);
            __nv_bfloat16 hs = __float2bfloat16_rn(vs);
            size_t o = (kcbase + l) * 64 + kk;
            g_B[0][o] = hr; g_B[1][o] = __float2bfloat16_rn(vr - __bfloat162float(hr));
            g_B[2][o] = hi; g_B[3][o] = __float2bfloat16_rn(vi - __bfloat162float(hi));
            g_B[4][o] = hs; g_B[5][o] = __float2bfloat16_rn(vs - __bfloat162float(hs));
            float nvr = vr * ab.x - vi * ab.y;
            float nvi = vr * ab.y + vi * ab.x;
            vr = nvr; vi = nvi;
        }
    } else {
        // ---- setupA: W[h,p] = C[h,p]*coef[p]*B[p,h], 3 variants hi/lo ----
        int idx = (blockIdx.x - 512) * 256 + threadIdx.x;   // over P*H
        int p = idx & (Pdim - 1), h = idx >> 10;
        float2 cf = g_cf[p];
        float br = B[(p * Hdim + h) * 2], bi = B[(p * Hdim + h) * 2 + 1];
        float bbr = cf.x * br - cf.y * bi;
        float bbi = cf.x * bi + cf.y * br;
        float cr = C[(h * Pdim + p) * 2], ci = C[(h * Pdim + p) * 2 + 1];
        float wr = cr * bbr - ci * bbi;
        float wi = cr * bbi + ci * bbr;
        float ws = wr + wi;

        size_t o = ((size_t)(p >> 6) * 256 + h) * 64 + (p & 63);
        __nv_bfloat16 hr = __float2bfloat16_rn(wr);
        __nv_bfloat16 hi = __float2bfloat16_rn(wi);
        __nv_bfloat16 hs = __float2bfloat16_rn(ws);
        g_A[0][o] = hr; g_A[1][o] = __float2bfloat16_rn(wr - __bfloat162float(hr));
        g_A[2][o] = hi; g_A[3][o] = __float2bfloat16_rn(wi - __bfloat162float(hi));
        g_A[4][o] = hs; g_A[5][o] = __float2bfloat16_rn(ws - __bfloat162float(hs));
    }
}

// ---------------------------------------------------------------------------
// k_gemm: z-batched 3 real GEMMs, CTA tile 128m x 256n, 512 thr (16 warps
// 2m x 8n, warp tile 64m x 32n), 2-stage cp.async pipeline (192 KB smem).
// Register-lifetime-scheduled products per ks-step:
//   (1) a_hi[0..3] + b_hi live -> 16 MMA hi*hi
//   (2) stream a_lo one frag at a time vs b_hi -> 16 MMA lo*hi
//   (3) b_lo replaces b_hi, a_hi still live -> 16 MMA hi*lo
// Max live frags = 28 regs (vs R7's 48) -> no spill at 128-reg cap.
// Stage layout: [Ahi 16K][Alo 16K][Bhi 32K][Blo 32K].
// ---------------------------------------------------------------------------
__global__ __launch_bounds__(512, 1) void k_gemm() {
    extern __shared__ char smp[];
    const int tid  = threadIdx.x;
    const int lane = tid & 31;
    const int wid  = tid >> 5;
    const int wm   = wid >> 3;            // 0..1 (m 64 each)
    const int wn   = wid & 7;             // 0..7 (n 32 each)
    const int m0   = blockIdx.x * 128;
    const int n0   = blockIdx.y * 256;
    const int z    = blockIdx.z;          // 0=r, 1=i, 2=s
    const uint32_t sb = s2u(smp);

    const __nv_bfloat16* Agh = g_A[2 * z];
    const __nv_bfloat16* Agl = g_A[2 * z + 1];
    const __nv_bfloat16* Bgh = g_B[2 * z];
    const __nv_bfloat16* Bgl = g_B[2 * z + 1];

    float acc[4][4][4];                   // [m-frag][n-frag][quad]
    #pragma unroll
    for (int i = 0; i < 4; i++)
        #pragma unroll
        for (int j = 0; j < 4; j++)
            #pragma unroll
            for (int t = 0; t < 4; t++) acc[i][j][t] = 0.0f;

    // cp.async staging: A planes 128x8 slots (2/thread/plane),
    //                   B planes 256x8 slots (4/thread/plane)
    const int arow = tid >> 2, acol = tid & 3;
    const int brow = tid >> 1, bcol = tid & 1;

    auto issue = [&](int kc, int s) {
        uint32_t st = sb + s * STAGE_BYTES;
        #pragma unroll
        for (int j = 0; j < 2; j++) {
            int col = acol + 4 * j;
            uint32_t d = st + arow * 128 + ((col ^ (arow & 7)) << 4);
            size_t oA = ((size_t)kc * 256 + m0 + arow) * 64 + col * 8;
            cpa(d,         Agh + oA);
            cpa(d + 16384, Agl + oA);
        }
        #pragma unroll
        for (int j = 0; j < 4; j++) {
            int col = bcol + 2 * j;
            uint32_t d = st + 32768 + brow * 128 + ((col ^ (brow & 7)) << 4);
            size_t oB = ((size_t)kc * 16384 + n0 + brow) * 64 + col * 8;
            cpa(d,         Bgh + oB);
            cpa(d + 32768, Bgl + oB);
        }
        asm volatile("cp.async.commit_group;" ::: "memory");
    };

    const int r15 = lane & 15, h16 = lane >> 4;
    const int rA = wm * 64 + r15;          // A m-frag rows rA + 16*im
    const int rB = wn * 32 + r15;          // B rows rB, rB+16

    issue(0, 0);

    for (int k = 0; k < NKC; k++) {
        const int s = k & 1;
        if (k + 1 < NKC) {
            issue(k + 1, s ^ 1);
            asm volatile("cp.async.wait_group 1;" ::: "memory");
        } else {
            asm volatile("cp.async.wait_group 0;" ::: "memory");
        }
        __syncthreads();

        const uint32_t sA = sb + s * STAGE_BYTES;          // A hi (lo at +16384)
        const uint32_t sB = sA + 32768;                     // B hi (lo at +32768)

        #pragma unroll
        for (int ks = 0; ks < 4; ks++) {
            const int cc = 2 * ks + h16;
            const uint32_t swA0 = ((cc ^ (rA & 7)) << 4);
            const uint32_t oB = rB * 128 + ((cc ^ (rB & 7)) << 4);

            uint32_t ah[16], bb[8], alt[4];

            // (1) a_hi[0..3] and b_hi live
            #pragma unroll
            for (int im = 0; im < 4; im++)
                ldm4(&ah[4 * im], sA + (rA + 16 * im) * 128 + swA0);
            ldm4(&bb[0], sB + oB);
            ldm4(&bb[4], sB + oB + 2048);

            #pragma unroll
            for (int im = 0; im < 4; im++) {
                mma16816(acc[im][0], &ah[4 * im], bb[0], bb[2]);
                mma16816(acc[im][1], &ah[4 * im], bb[1], bb[3]);
                mma16816(acc[im][2], &ah[4 * im], bb[4], bb[6]);
                mma16816(acc[im][3], &ah[4 * im], bb[5], bb[7]);
            }
            // (2) stream a_lo frags vs b_hi
            #pragma unroll
            for (int im = 0; im < 4; im++) {
                ldm4(alt, sA + 16384 + (rA + 16 * im) * 128 + swA0);
                mma16816(acc[im][0], alt, bb[0], bb[2]);
                mma16816(acc[im][1], alt, bb[1], bb[3]);
                mma16816(acc[im][2], alt, bb[4], bb[6]);
                mma16816(acc[im][3], alt, bb[5], bb[7]);
            }
            // (3) b_lo replaces b_hi; a_hi still live
            ldm4(&bb[0], sB + 32768 + oB);
            ldm4(&bb[4], sB + 32768 + oB + 2048);
            #pragma unroll
            for (int im = 0; im < 4; im++) {
                mma16816(acc[im][0], &ah[4 * im], bb[0], bb[2]);
                mma16816(acc[im][1], &ah[4 * im], bb[1], bb[3]);
                mma16816(acc[im][2], &ah[4 * im], bb[4], bb[6]);
                mma16816(acc[im][3], &ah[4 * im], bb[5], bb[7]);
            }
        }
        __syncthreads();
    }

    // Epilogue -> fp32 partial plane
    float* G = g_G[z];
    const int mrow = lane >> 2, ncol = (lane & 3) * 2;
    #pragma unroll
    for (int im = 0; im < 4; im++) {
        int m = m0 + wm * 64 + im * 16 + mrow;
        #pragma unroll
        for (int jn = 0; jn < 4; jn++) {
            int n = n0 + wn * 32 + jn * 8 + ncol;
            float* p = G + (size_t)m * Ldim + n;
            *(float2*)p = make_float2(acc[im][jn][0], acc[im][jn][1]);
            *(float2*)(p + (size_t)8 * Ldim) = make_float2(acc[im][jn][2], acc[im][jn][3]);
        }
    }
}

// ---------------------------------------------------------------------------
// k_comb: out[h][l] = (Gr-Gi, Gm-Gr-Gi), vectorized float4.
// ---------------------------------------------------------------------------
__global__ void k_comb(float4* __restrict__ out) {
    size_t idx = (size_t)blockIdx.x * 256 + threadIdx.x;   // over H*L/4
    const float4* Gr = (const float4*)g_G[0];
    const float4* Gi = (const float4*)g_G[1];
    const float4* Gm = (const float4*)g_G[2];
    float4 r = Gr[idx], i = Gi[idx], m = Gm[idx];
    out[2 * idx] = make_float4(r.x - i.x, m.x - r.x - i.x,
                               r.y - i.y, m.y - r.y - i.y);
    out[2 * idx + 1] = make_float4(r.z - i.z, m.z - r.z - i.z,
                                   r.w - i.w, m.w - r.w - i.w);
}

// ---------------------------------------------------------------------------
extern "C" void kernel_launch(void* const* d_in, const int* in_sizes, int n_in,
                              void* d_out, int out_size) {
    const float* A = (const float*)d_in[0];
    const float* B = (const float*)d_in[1];
    const float* C = (const float*)d_in[2];

    cudaFuncSetAttribute(k_gemm, cudaFuncAttributeMaxDynamicSharedMemorySize, 196608);

    k_pre<<<4, 256>>>(A);
    k_fill<<<1536, 256>>>(B, C);
    k_gemm<<<dim3(2, 64, 3), 512, 196608>>>();
    k_comb<<<4096, 256>>>((float4*)d_out);
}

// round 9
// speedup vs baseline: 1.1306x; 1.1306x over previous
#include <cuda_runtime.h>
#include <cuda_bf16.h>
#include <math.h>
#include <stdint.h>

#define DTC 0.001
#define Pdim 1024
#define Hdim 256
#define Ldim 16384
#define NKC  16             // K chunks of 64 (K = 1024 per GEMM)
#define STAGE_BYTES 65536   // Ahi 16K | Alo 16K | Bhi 16K | Blo 16K

// ---------------------------------------------------------------------------
// Device-global scratch (allocation-free rule)
// ---------------------------------------------------------------------------
__device__ __align__(16) float2  g_ab[Pdim];     // fp32 A_bar
__device__ __align__(16) float2  g_cf[Pdim];     // (A_bar-1)/Ac
__device__ __align__(16) double2 g_lg[Pdim];     // log(A_bar) fp64
// A planes [variant: r_hi, r_lo, i_hi, i_lo, s_hi, s_lo][kc(16)][m=h(256)][kk(64)]
// plane byte stride = 16*256*64*2 = 524288
__device__ __align__(128) __nv_bfloat16 g_A[6][(size_t)16 * 256 * 64];
// B planes same order, [kc(16)][n=l(16384)][kk(64)]; plane stride 33554432 B
__device__ __align__(128) __nv_bfloat16 g_B[6][(size_t)16 * 16384 * 64];
// Partial GEMM outputs Gr, Gi, Gm  (16 MB each)
__device__ __align__(128) float g_G[3][(size_t)256 * 16384];

// ---------------------------------------------------------------------------
// helpers
// ---------------------------------------------------------------------------
__device__ __forceinline__ uint32_t s2u(const void* p) {
    uint32_t a;
    asm("{ .reg .u64 t; cvta.to.shared.u64 t, %1; cvt.u32.u64 %0, t; }"
        : "=r"(a) : "l"(p));
    return a;
}

// cp.async with compile-time byte offsets on both operands
template <int DOFF, int SOFF>
__device__ __forceinline__ void cpa(uint32_t dst, const char* src) {
    asm volatile("cp.async.cg.shared.global [%0+%2], [%1+%3], 16;"
                 :: "r"(dst), "l"(src), "n"(DOFF), "n"(SOFF) : "memory");
}

// ldmatrix.x4 with compile-time byte offset
template <int OFF>
__device__ __forceinline__ void ldm4(uint32_t* r, uint32_t a) {
    asm volatile("ldmatrix.sync.aligned.m8n8.x4.shared.b16 {%0,%1,%2,%3}, [%4+%5];"
                 : "=r"(r[0]), "=r"(r[1]), "=r"(r[2]), "=r"(r[3])
                 : "r"(a), "n"(OFF));
}

__device__ __forceinline__ void mma16816(float* d, const uint32_t* a,
                                         uint32_t b0, uint32_t b1) {
    asm volatile(
        "mma.sync.aligned.m16n8k16.row.col.f32.bf16.bf16.f32 "
        "{%0,%1,%2,%3}, {%4,%5,%6,%7}, {%8,%9}, {%0,%1,%2,%3};"
        : "+f"(d[0]), "+f"(d[1]), "+f"(d[2]), "+f"(d[3])
        : "r"(a[0]), "r"(a[1]), "r"(a[2]), "r"(a[3]), "r"(b0), "r"(b1));
}

// ---------------------------------------------------------------------------
// k_pre: per-p constants (fp64 transcendentals once per p)
// ---------------------------------------------------------------------------
__global__ void k_pre(const float* __restrict__ A) {
    int p = blockIdx.x * blockDim.x + threadIdx.x;
    if (p >= Pdim) return;
    float ar = A[2 * p], ai = A[2 * p + 1];
    double e = exp((double)ar * DTC), th = (double)ai * DTC;
    float abr = (float)(e * cos(th));
    float abi = (float)(e * sin(th));
    float nr = abr - 1.0f, ni = abi;
    float den = ar * ar + ai * ai;
    g_ab[p] = make_float2(abr, abi);
    g_cf[p] = make_float2((nr * ar + ni * ai) / den, (ni * ar - nr * ai) / den);
    g_lg[p] = make_double2(0.5 * log((double)abr * abr + (double)abi * abi),
                           atan2((double)abi, (double)abr));
}

// ---------------------------------------------------------------------------
// k_fill: merged B-generation (blocks 0..511) + A-setup (blocks 512..1535)
// ---------------------------------------------------------------------------
__global__ void k_fill(const float* __restrict__ B, const float* __restrict__ C) {
    if (blockIdx.x < 512) {
        int wid = blockIdx.x * 8 + (threadIdx.x >> 5);   // 4096 warps
        int lane = threadIdx.x & 31;
        int pg = wid & 31, seg = wid >> 5;               // seg 0..127
        int p = pg * 32 + lane;

        float2 ab = g_ab[p];
        double2 lg = g_lg[p];
        int l0 = seg * 128;
        double m = exp(lg.x * (double)l0), a = lg.y * (double)l0;
        float vr = (float)(m * cos(a));
        float vi = (float)(m * sin(a));

        const size_t kcbase = (size_t)(p >> 6) * 16384;
        const int kk = p & 63;

        #pragma unroll 4
        for (int t = 0; t < 128; t++) {
            int l = l0 + t;
            float vs = vr + vi;
            __nv_bfloat16 hr = __float2bfloat16_rn(vr);
            __nv_bfloat16 hi = __float2bfloat16_rn(vi);
            __nv_bfloat16 hs = __float2bfloat16_rn(vs);
            size_t o = (kcbase + l) * 64 + kk;
            g_B[0][o] = hr; g_B[1][o] = __float2bfloat16_rn(vr - __bfloat162float(hr));
            g_B[2][o] = hi; g_B[3][o] = __float2bfloat16_rn(vi - __bfloat162float(hi));
            g_B[4][o] = hs; g_B[5][o] = __float2bfloat16_rn(vs - __bfloat162float(hs));
            float nvr = vr * ab.x - vi * ab.y;
            float nvi = vr * ab.y + vi * ab.x;
            vr = nvr; vi = nvi;
        }
    } else {
        int idx = (blockIdx.x - 512) * 256 + threadIdx.x;   // over P*H
        int p = idx & (Pdim - 1), h = idx >> 10;
        float2 cf = g_cf[p];
        float br = B[(p * Hdim + h) * 2], bi = B[(p * Hdim + h) * 2 + 1];
        float bbr = cf.x * br - cf.y * bi;
        float bbi = cf.x * bi + cf.y * br;
        float cr = C[(h * Pdim + p) * 2], ci = C[(h * Pdim + p) * 2 + 1];
        float wr = cr * bbr - ci * bbi;
        float wi = cr * bbi + ci * bbr;
        float ws = wr + wi;

        size_t o = ((size_t)(p >> 6) * 256 + h) * 64 + (p & 63);
        __nv_bfloat16 hr = __float2bfloat16_rn(wr);
        __nv_bfloat16 hi = __float2bfloat16_rn(wi);
        __nv_bfloat16 hs = __float2bfloat16_rn(ws);
        g_A[0][o] = hr; g_A[1][o] = __float2bfloat16_rn(wr - __bfloat162float(hr));
        g_A[2][o] = hi; g_A[3][o] = __float2bfloat16_rn(wi - __bfloat162float(hi));
        g_A[4][o] = hs; g_A[5][o] = __float2bfloat16_rn(ws - __bfloat162float(hs));
    }
}

// ---------------------------------------------------------------------------
// k_gemm: z-batched 3 real GEMMs, R5 shape (CTA 128m x 128n, 512 thr, 16
// warps 4x4, warp 32x32), 2-stage cp.async pipeline, ADDRESSING DIET:
//   - stage select k&1 with unroll 2 (compile-time stage bases)
//   - global srcs via 2 running pointers + PTX immediate offsets
//   - ldmatrix offsets precomputed (8 regs), variants via [reg+imm]
// Stage: [Ahi 16K][Alo 16K][Bhi 16K][Blo 16K].
// ---------------------------------------------------------------------------
__global__ __launch_bounds__(512, 1) void k_gemm() {
    extern __shared__ char smp[];
    const int tid  = threadIdx.x;
    const int lane = tid & 31;
    const int wid  = tid >> 5;
    const int wm   = wid >> 2;            // 0..3
    const int wn   = wid & 3;             // 0..3
    const int m0   = blockIdx.x * 128;
    const int n0   = blockIdx.y * 128;
    const int z    = blockIdx.z;          // 0=r, 1=i, 2=s
    const uint32_t sb = s2u(smp);

    float acc[2][4][4];
    #pragma unroll
    for (int i = 0; i < 2; i++)
        #pragma unroll
        for (int j = 0; j < 4; j++)
            #pragma unroll
            for (int t = 0; t < 4; t++) acc[i][j][t] = 0.0f;

    // ---- cp.async mapping: row = tid>>3 (0..63, +64), col = tid&7 ----
    const int crow = tid >> 3;
    const int ccol = tid & 7;
    // per-thread smem dst base (stage 0); A region. B region at +32768.
    const uint32_t dA0 = sb + crow * 128 + ((ccol ^ (crow & 7)) << 4);
    const uint32_t dA1 = dA0 + STAGE_BYTES;
    // per-thread global byte offsets (chunk 0)
    const char* pA = (const char*)g_A[2 * z] +
                     (((size_t)(m0 + crow) * 64 + ccol * 8) * 2);
    const char* pB = (const char*)g_B[2 * z] +
                     (((size_t)(n0 + crow) * 64 + ccol * 8) * 2);

    // A plane (hi->lo) byte stride 524288; B plane stride 33554432.
    // second row (+64): +8192 both in smem and in global (64*64*2).
    auto issue = [&](uint32_t dA) {
        cpa<0,          0>(dA, pA);
        cpa<8192,    8192>(dA, pA);
        cpa<16384,      0>(dA, pA + 524288);
        cpa<24576,   8192>(dA, pA + 524288);
        cpa<32768,      0>(dA, pB);
        cpa<40960,   8192>(dA, pB);
        cpa<49152,      0>(dA, pB + 33554432);
        cpa<57344,   8192>(dA, pB + 33554432);
        asm volatile("cp.async.commit_group;" ::: "memory");
        pA += 32768;         // 256 rows * 64 * 2
        pB += 2097152;       // 16384 rows * 64 * 2
    };

    // ---- ldmatrix offsets (loop-invariant): 4 ks x {A, B} ----
    const int r15 = lane & 15, h16 = lane >> 4;
    const int rA = wm * 32 + r15;          // rows rA, rA+16 (same swizzle)
    const int rB = wn * 32 + r15;
    uint32_t oA[4], oB[4];
    #pragma unroll
    for (int ks = 0; ks < 4; ks++) {
        const int cc = 2 * ks + h16;
        oA[ks] = (uint32_t)(rA * 128 + ((cc ^ (rA & 7)) << 4));
        oB[ks] = (uint32_t)(rB * 128 + ((cc ^ (rB & 7)) << 4)) + 32768u;
    }

    issue(dA0);

    #pragma unroll 2
    for (int k = 0; k < NKC; k++) {
        const uint32_t stage = sb + (uint32_t)((k & 1) * STAGE_BYTES);
        if (k + 1 < NKC) {
            issue((k & 1) ? dA0 : dA1);
            asm volatile("cp.async.wait_group 1;" ::: "memory");
        } else {
            asm volatile("cp.async.wait_group 0;" ::: "memory");
        }
        __syncthreads();

        #pragma unroll
        for (int ks = 0; ks < 4; ks++) {
            const uint32_t aAddr = stage + oA[ks];
            const uint32_t bAddr = stage + oB[ks];

            uint32_t a0[4], a1[4], al0[4], al1[4];
            uint32_t bh0[4], bh1[4], bl0[4], bl1[4];
            ldm4<0>     (a0,  aAddr);
            ldm4<2048>  (a1,  aAddr);
            ldm4<16384> (al0, aAddr);
            ldm4<18432> (al1, aAddr);
            ldm4<0>     (bh0, bAddr);
            ldm4<2048>  (bh1, bAddr);
            ldm4<16384> (bl0, bAddr);
            ldm4<18432> (bl1, bAddr);

            // hi*hi
            mma16816(acc[0][0], a0, bh0[0], bh0[2]);
            mma16816(acc[0][1], a0, bh0[1], bh0[3]);
            mma16816(acc[0][2], a0, bh1[0], bh1[2]);
            mma16816(acc[0][3], a0, bh1[1], bh1[3]);
            mma16816(acc[1][0], a1, bh0[0], bh0[2]);
            mma16816(acc[1][1], a1, bh0[1], bh0[3]);
            mma16816(acc[1][2], a1, bh1[0], bh1[2]);
            mma16816(acc[1][3], a1, bh1[1], bh1[3]);
            // hi*lo
            mma16816(acc[0][0], a0, bl0[0], bl0[2]);
            mma16816(acc[0][1], a0, bl0[1], bl0[3]);
            mma16816(acc[0][2], a0, bl1[0], bl1[2]);
            mma16816(acc[0][3], a0, bl1[1], bl1[3]);
            mma16816(acc[1][0], a1, bl0[0], bl0[2]);
            mma16816(acc[1][1], a1, bl0[1], bl0[3]);
            mma16816(acc[1][2], a1, bl1[0], bl1[2]);
            mma16816(acc[1][3], a1, bl1[1], bl1[3]);
            // lo*hi
            mma16816(acc[0][0], al0, bh0[0], bh0[2]);
            mma16816(acc[0][1], al0, bh0[1], bh0[3]);
            mma16816(acc[0][2], al0, bh1[0], bh1[2]);
            mma16816(acc[0][3], al0, bh1[1], bh1[3]);
            mma16816(acc[1][0], al1, bh0[0], bh0[2]);
            mma16816(acc[1][1], al1, bh0[1], bh0[3]);
            mma16816(acc[1][2], al1, bh1[0], bh1[2]);
            mma16816(acc[1][3], al1, bh1[1], bh1[3]);
        }
        __syncthreads();
    }

    // Epilogue -> fp32 partial plane
    float* G = g_G[z];
    const int mrow = lane >> 2, ncol = (lane & 3) * 2;
    #pragma unroll
    for (int im = 0; im < 2; im++) {
        int m = m0 + wm * 32 + im * 16 + mrow;
        #pragma unroll
        for (int jn = 0; jn < 4; jn++) {
            int n = n0 + wn * 32 + jn * 8 + ncol;
            float* p = G + (size_t)m * Ldim + n;
            *(float2*)p = make_float2(acc[im][jn][0], acc[im][jn][1]);
            *(float2*)(p + (size_t)8 * Ldim) = make_float2(acc[im][jn][2], acc[im][jn][3]);
        }
    }
}

// ---------------------------------------------------------------------------
// k_comb: out[h][l] = (Gr-Gi, Gm-Gr-Gi), vectorized float4.
// ---------------------------------------------------------------------------
__global__ void k_comb(float4* __restrict__ out) {
    size_t idx = (size_t)blockIdx.x * 256 + threadIdx.x;   // over H*L/4
    const float4* Gr = (const float4*)g_G[0];
    const float4* Gi = (const float4*)g_G[1];
    const float4* Gm = (const float4*)g_G[2];
    float4 r = Gr[idx], i = Gi[idx], m = Gm[idx];
    out[2 * idx] = make_float4(r.x - i.x, m.x - r.x - i.x,
                               r.y - i.y, m.y - r.y - i.y);
    out[2 * idx + 1] = make_float4(r.z - i.z, m.z - r.z - i.z,
                                   r.w - i.w, m.w - r.w - i.w);
}

// ---------------------------------------------------------------------------
extern "C" void kernel_launch(void* const* d_in, const int* in_sizes, int n_in,
                              void* d_out, int out_size) {
    const float* A = (const float*)d_in[0];
    const float* B = (const float*)d_in[1];
    const float* C = (const float*)d_in[2];

    cudaFuncSetAttribute(k_gemm, cudaFuncAttributeMaxDynamicSharedMemorySize, 131072);

    k_pre<<<4, 256>>>(A);
    k_fill<<<1536, 256>>>(B, C);
    k_gemm<<<dim3(2, 128, 3), 512, 131072>>>();
    k_comb<<<4096, 256>>>((float4*)d_out);
}

// round 10
// speedup vs baseline: 2.2886x; 2.0242x over previous
#include <cuda_runtime.h>
#include <cuda_fp16.h>
#include <math.h>
#include <stdint.h>

#define DTC 0.001
#define Pdim 1024
#define Hdim 256
#define Ldim 16384
#define NKC  16             // K chunks of 64 (K = 1024 per GEMM)
#define STAGE_BYTES 32768   // A 16K | B 16K
#define WSCALE 65536.0f
#define INV_WSCALE 1.52587890625e-05f

// ---------------------------------------------------------------------------
// Device-global scratch (allocation-free rule)
// ---------------------------------------------------------------------------
__device__ __align__(16) float2  g_ab[Pdim];     // fp32 A_bar
__device__ __align__(16) float2  g_cf[Pdim];     // (A_bar-1)/Ac
__device__ __align__(16) double2 g_lg[Pdim];     // log(A_bar) fp64
// A planes [variant: r, i, r+i][kc(16)][m=h(256)][kk(64)] fp16 (W scaled by 2^16)
__device__ __align__(128) __half g_A[3][(size_t)16 * 256 * 64];
// B planes [variant: r, i, r+i][kc(16)][n=l(16384)][kk(64)] fp16 (32 MB each)
__device__ __align__(128) __half g_B[3][(size_t)16 * 16384 * 64];
// Partial GEMM outputs Gr, Gi, Gm  (16 MB each)
__device__ __align__(128) float g_G[3][(size_t)256 * 16384];

// ---------------------------------------------------------------------------
// helpers
// ---------------------------------------------------------------------------
__device__ __forceinline__ uint32_t s2u(const void* p) {
    uint32_t a;
    asm("{ .reg .u64 t; cvta.to.shared.u64 t, %1; cvt.u32.u64 %0, t; }"
        : "=r"(a) : "l"(p));
    return a;
}

template <int DOFF, int SOFF>
__device__ __forceinline__ void cpa(uint32_t dst, const char* src) {
    asm volatile("cp.async.cg.shared.global [%0+%2], [%1+%3], 16;"
                 :: "r"(dst), "l"(src), "n"(DOFF), "n"(SOFF) : "memory");
}

template <int OFF>
__device__ __forceinline__ void ldm4(uint32_t* r, uint32_t a) {
    asm volatile("ldmatrix.sync.aligned.m8n8.x4.shared.b16 {%0,%1,%2,%3}, [%4+%5];"
                 : "=r"(r[0]), "=r"(r[1]), "=r"(r[2]), "=r"(r[3])
                 : "r"(a), "n"(OFF));
}

__device__ __forceinline__ void mma16816(float* d, const uint32_t* a,
                                         uint32_t b0, uint32_t b1) {
    asm volatile(
        "mma.sync.aligned.m16n8k16.row.col.f32.f16.f16.f32 "
        "{%0,%1,%2,%3}, {%4,%5,%6,%7}, {%8,%9}, {%0,%1,%2,%3};"
        : "+f"(d[0]), "+f"(d[1]), "+f"(d[2]), "+f"(d[3])
        : "r"(a[0]), "r"(a[1]), "r"(a[2]), "r"(a[3]), "r"(b0), "r"(b1));
}

// ---------------------------------------------------------------------------
// k_pre: per-p constants (fp64 transcendentals once per p)
// ---------------------------------------------------------------------------
__global__ void k_pre(const float* __restrict__ A) {
    int p = blockIdx.x * blockDim.x + threadIdx.x;
    if (p >= Pdim) return;
    float ar = A[2 * p], ai = A[2 * p + 1];
    double e = exp((double)ar * DTC), th = (double)ai * DTC;
    float abr = (float)(e * cos(th));
    float abi = (float)(e * sin(th));
    float nr = abr - 1.0f, ni = abi;
    float den = ar * ar + ai * ai;
    g_ab[p] = make_float2(abr, abi);
    g_cf[p] = make_float2((nr * ar + ni * ai) / den, (ni * ar - nr * ai) / den);
    g_lg[p] = make_double2(0.5 * log((double)abr * abr + (double)abi * abi),
                           atan2((double)abi, (double)abr));
}

// ---------------------------------------------------------------------------
// k_fill: merged B-generation (blocks 0..511) + A-setup (blocks 512..1535)
// V fp16 direct; W scaled by 2^16 then fp16 (avoids fp16 subnormals).
// ---------------------------------------------------------------------------
__global__ void k_fill(const float* __restrict__ B, const float* __restrict__ C) {
    if (blockIdx.x < 512) {
        int wid = blockIdx.x * 8 + (threadIdx.x >> 5);   // 4096 warps
        int lane = threadIdx.x & 31;
        int pg = wid & 31, seg = wid >> 5;               // seg 0..127
        int p = pg * 32 + lane;

        float2 ab = g_ab[p];
        double2 lg = g_lg[p];
        int l0 = seg * 128;
        double m = exp(lg.x * (double)l0), a = lg.y * (double)l0;
        float vr = (float)(m * cos(a));
        float vi = (float)(m * sin(a));

        const size_t kcbase = (size_t)(p >> 6) * 16384;
        const int kk = p & 63;

        #pragma unroll 4
        for (int t = 0; t < 128; t++) {
            int l = l0 + t;
            size_t o = (kcbase + l) * 64 + kk;
            g_B[0][o] = __float2half_rn(vr);
            g_B[1][o] = __float2half_rn(vi);
            g_B[2][o] = __float2half_rn(vr + vi);
            float nvr = vr * ab.x - vi * ab.y;
            float nvi = vr * ab.y + vi * ab.x;
            vr = nvr; vi = nvi;
        }
    } else {
        int idx = (blockIdx.x - 512) * 256 + threadIdx.x;   // over P*H
        int p = idx & (Pdim - 1), h = idx >> 10;
        float2 cf = g_cf[p];
        float br = B[(p * Hdim + h) * 2], bi = B[(p * Hdim + h) * 2 + 1];
        float bbr = cf.x * br - cf.y * bi;
        float bbi = cf.x * bi + cf.y * br;
        float cr = C[(h * Pdim + p) * 2], ci = C[(h * Pdim + p) * 2 + 1];
        float wr = (cr * bbr - ci * bbi) * WSCALE;
        float wi = (cr * bbi + ci * bbr) * WSCALE;

        size_t o = ((size_t)(p >> 6) * 256 + h) * 64 + (p & 63);
        g_A[0][o] = __float2half_rn(wr);
        g_A[1][o] = __float2half_rn(wi);
        g_A[2][o] = __float2half_rn(wr + wi);
    }
}

// ---------------------------------------------------------------------------
// k_gemm: z-batched 3 real GEMMs, single fp16 product each. CTA 128m x 128n,
// 512 thr (16 warps 4x4, warp 32x32), 2-stage cp.async pipeline (64 KB smem).
// Per ks-step: 4 LDSM.x4 + 8 HMMA. Stage: [A 16K][B 16K].
// ---------------------------------------------------------------------------
__global__ __launch_bounds__(512, 1) void k_gemm() {
    extern __shared__ char smp[];
    const int tid  = threadIdx.x;
    const int lane = tid & 31;
    const int wid  = tid >> 5;
    const int wm   = wid >> 2;            // 0..3
    const int wn   = wid & 3;             // 0..3
    const int m0   = blockIdx.x * 128;
    const int n0   = blockIdx.y * 128;
    const int z    = blockIdx.z;          // 0=r, 1=i, 2=s
    const uint32_t sb = s2u(smp);

    float acc[2][4][4];
    #pragma unroll
    for (int i = 0; i < 2; i++)
        #pragma unroll
        for (int j = 0; j < 4; j++)
            #pragma unroll
            for (int t = 0; t < 4; t++) acc[i][j][t] = 0.0f;

    // ---- cp.async mapping: row = tid>>3 (0..63, +64), col = tid&7 ----
    const int crow = tid >> 3;
    const int ccol = tid & 7;
    const uint32_t dA0 = sb + crow * 128 + ((ccol ^ (crow & 7)) << 4);
    const uint32_t dA1 = dA0 + STAGE_BYTES;
    const char* pA = (const char*)g_A[z] +
                     (((size_t)(m0 + crow) * 64 + ccol * 8) * 2);
    const char* pB = (const char*)g_B[z] +
                     (((size_t)(n0 + crow) * 64 + ccol * 8) * 2);

    auto issue = [&](uint32_t dA) {
        cpa<0,        0>(dA, pA);
        cpa<8192,  8192>(dA, pA);
        cpa<16384,    0>(dA, pB);
        cpa<24576, 8192>(dA, pB);
        asm volatile("cp.async.commit_group;" ::: "memory");
        pA += 32768;         // 256 rows * 64 * 2
        pB += 2097152;       // 16384 rows * 64 * 2
    };

    // ---- ldmatrix offsets (loop-invariant): 4 ks x {A, B} ----
    const int r15 = lane & 15, h16 = lane >> 4;
    const int rA = wm * 32 + r15;
    const int rB = wn * 32 + r15;
    uint32_t oA[4], oB[4];
    #pragma unroll
    for (int ks = 0; ks < 4; ks++) {
        const int cc = 2 * ks + h16;
        oA[ks] = (uint32_t)(rA * 128 + ((cc ^ (rA & 7)) << 4));
        oB[ks] = (uint32_t)(rB * 128 + ((cc ^ (rB & 7)) << 4)) + 16384u;
    }

    issue(dA0);

    #pragma unroll 2
    for (int k = 0; k < NKC; k++) {
        const uint32_t stage = sb + (uint32_t)((k & 1) * STAGE_BYTES);
        if (k + 1 < NKC) {
            issue((k & 1) ? dA0 : dA1);
            asm volatile("cp.async.wait_group 1;" ::: "memory");
        } else {
            asm volatile("cp.async.wait_group 0;" ::: "memory");
        }
        __syncthreads();

        #pragma unroll
        for (int ks = 0; ks < 4; ks++) {
            const uint32_t aAddr = stage + oA[ks];
            const uint32_t bAddr = stage + oB[ks];

            uint32_t a0[4], a1[4], b0[4], b1[4];
            ldm4<0>    (a0, aAddr);
            ldm4<2048> (a1, aAddr);
            ldm4<0>    (b0, bAddr);
            ldm4<2048> (b1, bAddr);

            mma16816(acc[0][0], a0, b0[0], b0[2]);
            mma16816(acc[0][1], a0, b0[1], b0[3]);
            mma16816(acc[0][2], a0, b1[0], b1[2]);
            mma16816(acc[0][3], a0, b1[1], b1[3]);
            mma16816(acc[1][0], a1, b0[0], b0[2]);
            mma16816(acc[1][1], a1, b0[1], b0[3]);
            mma16816(acc[1][2], a1, b1[0], b1[2]);
            mma16816(acc[1][3], a1, b1[1], b1[3]);
        }
        __syncthreads();
    }

    // Epilogue -> fp32 partial plane
    float* G = g_G[z];
    const int mrow = lane >> 2, ncol = (lane & 3) * 2;
    #pragma unroll
    for (int im = 0; im < 2; im++) {
        int m = m0 + wm * 32 + im * 16 + mrow;
        #pragma unroll
        for (int jn = 0; jn < 4; jn++) {
            int n = n0 + wn * 32 + jn * 8 + ncol;
            float* p = G + (size_t)m * Ldim + n;
            *(float2*)p = make_float2(acc[im][jn][0], acc[im][jn][1]);
            *(float2*)(p + (size_t)8 * Ldim) = make_float2(acc[im][jn][2], acc[im][jn][3]);
        }
    }
}

// ---------------------------------------------------------------------------
// k_comb: out[h][l] = ((Gr-Gi), (Gm-Gr-Gi)) / 2^16, vectorized float4.
// ---------------------------------------------------------------------------
__global__ void k_comb(float4* __restrict__ out) {
    size_t idx = (size_t)blockIdx.x * 256 + threadIdx.x;   // over H*L/4
    const float4* Gr = (const float4*)g_G[0];
    const float4* Gi = (const float4*)g_G[1];
    const float4* Gm = (const float4*)g_G[2];
    float4 r = Gr[idx], i = Gi[idx], m = Gm[idx];
    out[2 * idx] = make_float4((r.x - i.x) * INV_WSCALE,
                               (m.x - r.x - i.x) * INV_WSCALE,
                               (r.y - i.y) * INV_WSCALE,
                               (m.y - r.y - i.y) * INV_WSCALE);
    out[2 * idx + 1] = make_float4((r.z - i.z) * INV_WSCALE,
                                   (m.z - r.z - i.z) * INV_WSCALE,
                                   (r.w - i.w) * INV_WSCALE,
                                   (m.w - r.w - i.w) * INV_WSCALE);
}

// ---------------------------------------------------------------------------
extern "C" void kernel_launch(void* const* d_in, const int* in_sizes, int n_in,
                              void* d_out, int out_size) {
    const float* A = (const float*)d_in[0];
    const float* B = (const float*)d_in[1];
    const float* C = (const float*)d_in[2];

    cudaFuncSetAttribute(k_gemm, cudaFuncAttributeMaxDynamicSharedMemorySize, 65536);

    k_pre<<<4, 256>>>(A);
    k_fill<<<1536, 256>>>(B, C);
    k_gemm<<<dim3(2, 128, 3), 512, 65536>>>();
    k_comb<<<4096, 256>>>((float4*)d_out);
}

// round 11
// speedup vs baseline: 2.3586x; 1.0306x over previous
#include <cuda_runtime.h>
#include <cuda_fp16.h>
#include <math.h>
#include <stdint.h>

#define DTC 0.001
#define Pdim 1024
#define Hdim 256
#define Ldim 16384
#define NKC  16             // K chunks of 64 (K = 1024)
#define STAGE_BYTES 81920   // Ar 16K | Ai 16K | Ami 16K | Vr 16K | Vi 16K
#define WSCALE 65536.0f
#define INV_WSCALE 1.52587890625e-05f

// ---------------------------------------------------------------------------
// Device-global scratch (allocation-free rule)
// ---------------------------------------------------------------------------
__device__ __align__(16) float2  g_ab[Pdim];     // fp32 A_bar
__device__ __align__(16) float2  g_cf[Pdim];     // (A_bar-1)/Ac
__device__ __align__(16) double2 g_lg[Pdim];     // log(A_bar) fp64
// A planes [0=Wr, 1=Wi, 2=-Wi][kc(16)][m=h(256)][kk(64)] fp16, scaled 2^16
// plane byte stride 524288
__device__ __align__(128) __half g_A[3][(size_t)16 * 256 * 64];
// B planes [0=Vr, 1=Vi][kc(16)][n=l(16384)][kk(64)] fp16; plane stride 33554432 B
__device__ __align__(128) __half g_B[2][(size_t)16 * 16384 * 64];

// ---------------------------------------------------------------------------
// helpers
// ---------------------------------------------------------------------------
__device__ __forceinline__ uint32_t s2u(const void* p) {
    uint32_t a;
    asm("{ .reg .u64 t; cvta.to.shared.u64 t, %1; cvt.u32.u64 %0, t; }"
        : "=r"(a) : "l"(p));
    return a;
}

template <int DOFF, int SOFF>
__device__ __forceinline__ void cpa(uint32_t dst, const char* src) {
    asm volatile("cp.async.cg.shared.global [%0+%2], [%1+%3], 16;"
                 :: "r"(dst), "l"(src), "n"(DOFF), "n"(SOFF) : "memory");
}

template <int OFF>
__device__ __forceinline__ void ldm4(uint32_t* r, uint32_t a) {
    asm volatile("ldmatrix.sync.aligned.m8n8.x4.shared.b16 {%0,%1,%2,%3}, [%4+%5];"
                 : "=r"(r[0]), "=r"(r[1]), "=r"(r[2]), "=r"(r[3])
                 : "r"(a), "n"(OFF));
}

__device__ __forceinline__ void mma16816(float* d, const uint32_t* a,
                                         uint32_t b0, uint32_t b1) {
    asm volatile(
        "mma.sync.aligned.m16n8k16.row.col.f32.f16.f16.f32 "
        "{%0,%1,%2,%3}, {%4,%5,%6,%7}, {%8,%9}, {%0,%1,%2,%3};"
        : "+f"(d[0]), "+f"(d[1]), "+f"(d[2]), "+f"(d[3])
        : "r"(a[0]), "r"(a[1]), "r"(a[2]), "r"(a[3]), "r"(b0), "r"(b1));
}

// ---------------------------------------------------------------------------
// k_pre: per-p constants (fp64 transcendentals once per p)
// ---------------------------------------------------------------------------
__global__ void k_pre(const float* __restrict__ A) {
    int p = blockIdx.x * blockDim.x + threadIdx.x;
    if (p >= Pdim) return;
    float ar = A[2 * p], ai = A[2 * p + 1];
    double e = exp((double)ar * DTC), th = (double)ai * DTC;
    float abr = (float)(e * cos(th));
    float abi = (float)(e * sin(th));
    float nr = abr - 1.0f, ni = abi;
    float den = ar * ar + ai * ai;
    g_ab[p] = make_float2(abr, abi);
    g_cf[p] = make_float2((nr * ar + ni * ai) / den, (ni * ar - nr * ai) / den);
    g_lg[p] = make_double2(0.5 * log((double)abr * abr + (double)abi * abi),
                           atan2((double)abi, (double)abr));
}

// ---------------------------------------------------------------------------
// k_fill: merged B-generation (blocks 0..511) + A-setup (blocks 512..1535)
// B planes: Vr, Vi fp16. A planes: Wr, Wi, -Wi fp16 (scaled 2^16).
// ---------------------------------------------------------------------------
__global__ void k_fill(const float* __restrict__ B, const float* __restrict__ C) {
    if (blockIdx.x < 512) {
        int wid = blockIdx.x * 8 + (threadIdx.x >> 5);   // 4096 warps
        int lane = threadIdx.x & 31;
        int pg = wid & 31, seg = wid >> 5;               // seg 0..127
        int p = pg * 32 + lane;

        float2 ab = g_ab[p];
        double2 lg = g_lg[p];
        int l0 = seg * 128;
        double m = exp(lg.x * (double)l0), a = lg.y * (double)l0;
        float vr = (float)(m * cos(a));
        float vi = (float)(m * sin(a));

        const size_t kcbase = (size_t)(p >> 6) * 16384;
        const int kk = p & 63;

        #pragma unroll 4
        for (int t = 0; t < 128; t++) {
            int l = l0 + t;
            size_t o = (kcbase + l) * 64 + kk;
            g_B[0][o] = __float2half_rn(vr);
            g_B[1][o] = __float2half_rn(vi);
            float nvr = vr * ab.x - vi * ab.y;
            float nvi = vr * ab.y + vi * ab.x;
            vr = nvr; vi = nvi;
        }
    } else {
        int idx = (blockIdx.x - 512) * 256 + threadIdx.x;   // over P*H
        int p = idx & (Pdim - 1), h = idx >> 10;
        float2 cf = g_cf[p];
        float br = B[(p * Hdim + h) * 2], bi = B[(p * Hdim + h) * 2 + 1];
        float bbr = cf.x * br - cf.y * bi;
        float bbi = cf.x * bi + cf.y * br;
        float cr = C[(h * Pdim + p) * 2], ci = C[(h * Pdim + p) * 2 + 1];
        float wr = (cr * bbr - ci * bbi) * WSCALE;
        float wi = (cr * bbi + ci * bbr) * WSCALE;

        size_t o = ((size_t)(p >> 6) * 256 + h) * 64 + (p & 63);
        g_A[0][o] = __float2half_rn(wr);
        g_A[1][o] = __float2half_rn(wi);
        g_A[2][o] = __float2half_rn(-wi);
    }
}

// ---------------------------------------------------------------------------
// k_gemm: fused 4-mult complex GEMM, direct interleaved output.
//   accR += Wr*Vr + (-Wi)*Vi ;  accI += Wi*Vr + Wr*Vi
// CTA 128m x 128n, 512 thr (16 warps 4x4, warp 32x32), 2-stage cp.async
// (160 KB smem). Per ks-step: 10 LDSM.x4 + 32 HMMA, frag-slot reuse keeps
// live regs ~105. Stage: [Ar 16K][Ai 16K][Ami 16K][Vr 16K][Vi 16K].
// ---------------------------------------------------------------------------
__global__ __launch_bounds__(512, 1) void k_gemm(float* __restrict__ out) {
    extern __shared__ char smp[];
    const int tid  = threadIdx.x;
    const int lane = tid & 31;
    const int wid  = tid >> 5;
    const int wm   = wid >> 2;            // 0..3
    const int wn   = wid & 3;             // 0..3
    const int m0   = blockIdx.x * 128;
    const int n0   = blockIdx.y * 128;
    const uint32_t sb = s2u(smp);

    float accR[2][4][4], accI[2][4][4];
    #pragma unroll
    for (int i = 0; i < 2; i++)
        #pragma unroll
        for (int j = 0; j < 4; j++)
            #pragma unroll
            for (int t = 0; t < 4; t++) { accR[i][j][t] = 0.0f; accI[i][j][t] = 0.0f; }

    // ---- cp.async mapping: row = tid>>3 (0..63, +64), col = tid&7 ----
    const int crow = tid >> 3;
    const int ccol = tid & 7;
    const uint32_t dA0 = sb + crow * 128 + ((ccol ^ (crow & 7)) << 4);
    const uint32_t dA1 = dA0 + STAGE_BYTES;
    const char* pA = (const char*)g_A[0] +
                     (((size_t)(m0 + crow) * 64 + ccol * 8) * 2);
    const char* pB = (const char*)g_B[0] +
                     (((size_t)(n0 + crow) * 64 + ccol * 8) * 2);

    auto issue = [&](uint32_t dA) {
        cpa<0,         0>(dA, pA);                 // Wr
        cpa<8192,   8192>(dA, pA);
        cpa<16384,     0>(dA, pA + 524288);        // Wi
        cpa<24576,  8192>(dA, pA + 524288);
        cpa<32768,     0>(dA, pA + 1048576);       // -Wi
        cpa<40960,  8192>(dA, pA + 1048576);
        cpa<49152,     0>(dA, pB);                 // Vr
        cpa<57344,  8192>(dA, pB);
        cpa<65536,     0>(dA, pB + 33554432);      // Vi
        cpa<73728,  8192>(dA, pB + 33554432);
        asm volatile("cp.async.commit_group;" ::: "memory");
        pA += 32768;         // 256 rows * 64 * 2
        pB += 2097152;       // 16384 rows * 64 * 2
    };

    // ---- ldmatrix offsets (loop-invariant): 4 ks x {A, B} ----
    const int r15 = lane & 15, h16 = lane >> 4;
    const int rA = wm * 32 + r15;
    const int rB = wn * 32 + r15;
    uint32_t oA[4], oB[4];
    #pragma unroll
    for (int ks = 0; ks < 4; ks++) {
        const int cc = 2 * ks + h16;
        oA[ks] = (uint32_t)(rA * 128 + ((cc ^ (rA & 7)) << 4));
        oB[ks] = (uint32_t)(rB * 128 + ((cc ^ (rB & 7)) << 4)) + 49152u;
    }

    issue(dA0);

    #pragma unroll 2
    for (int k = 0; k < NKC; k++) {
        const uint32_t stage = sb + (uint32_t)((k & 1) * STAGE_BYTES);
        if (k + 1 < NKC) {
            issue((k & 1) ? dA0 : dA1);
            asm volatile("cp.async.wait_group 1;" ::: "memory");
        } else {
            asm volatile("cp.async.wait_group 0;" ::: "memory");
        }
        __syncthreads();

        #pragma unroll
        for (int ks = 0; ks < 4; ks++) {
            const uint32_t aAddr = stage + oA[ks];
            const uint32_t bAddr = stage + oB[ks];

            uint32_t ar0[4], ar1[4], ax0[4], ax1[4], b0[4], b1[4];
            // phase 1: Wr, Wi vs Vr
            ldm4<0>     (ar0, aAddr);              // Wr rows rA
            ldm4<2048>  (ar1, aAddr);              // Wr rows rA+16
            ldm4<16384> (ax0, aAddr);              // Wi
            ldm4<18432> (ax1, aAddr);
            ldm4<0>     (b0, bAddr);               // Vr
            ldm4<2048>  (b1, bAddr);

            mma16816(accR[0][0], ar0, b0[0], b0[2]);
            mma16816(accR[0][1], ar0, b0[1], b0[3]);
            mma16816(accR[0][2], ar0, b1[0], b1[2]);
            mma16816(accR[0][3], ar0, b1[1], b1[3]);
            mma16816(accR[1][0], ar1, b0[0], b0[2]);
            mma16816(accR[1][1], ar1, b0[1], b0[3]);
            mma16816(accR[1][2], ar1, b1[0], b1[2]);
            mma16816(accR[1][3], ar1, b1[1], b1[3]);
            mma16816(accI[0][0], ax0, b0[0], b0[2]);
            mma16816(accI[0][1], ax0, b0[1], b0[3]);
            mma16816(accI[0][2], ax0, b1[0], b1[2]);
            mma16816(accI[0][3], ax0, b1[1], b1[3]);
            mma16816(accI[1][0], ax1, b0[0], b0[2]);
            mma16816(accI[1][1], ax1, b0[1], b0[3]);
            mma16816(accI[1][2], ax1, b1[0], b1[2]);
            mma16816(accI[1][3], ax1, b1[1], b1[3]);

            // phase 2: reuse slots -> -Wi and Vi
            ldm4<32768> (ax0, aAddr);              // -Wi
            ldm4<34816> (ax1, aAddr);
            ldm4<16384> (b0, bAddr);               // Vi
            ldm4<18432> (b1, bAddr);

            mma16816(accI[0][0], ar0, b0[0], b0[2]);
            mma16816(accI[0][1], ar0, b0[1], b0[3]);
            mma16816(accI[0][2], ar0, b1[0], b1[2]);
            mma16816(accI[0][3], ar0, b1[1], b1[3]);
            mma16816(accI[1][0], ar1, b0[0], b0[2]);
            mma16816(accI[1][1], ar1, b0[1], b0[3]);
            mma16816(accI[1][2], ar1, b1[0], b1[2]);
            mma16816(accI[1][3], ar1, b1[1], b1[3]);
            mma16816(accR[0][0], ax0, b0[0], b0[2]);
            mma16816(accR[0][1], ax0, b0[1], b0[3]);
            mma16816(accR[0][2], ax0, b1[0], b1[2]);
            mma16816(accR[0][3], ax0, b1[1], b1[3]);
            mma16816(accR[1][0], ax1, b0[0], b0[2]);
            mma16816(accR[1][1], ax1, b0[1], b0[3]);
            mma16816(accR[1][2], ax1, b1[0], b1[2]);
            mma16816(accR[1][3], ax1, b1[1], b1[3]);
        }
        __syncthreads();
    }

    // Epilogue: interleaved (re, im) float4 writes, n == l.
    const int mrow = lane >> 2, ncol = (lane & 3) * 2;
    #pragma unroll
    for (int im = 0; im < 2; im++) {
        int m = m0 + wm * 32 + im * 16 + mrow;
        #pragma unroll
        for (int jn = 0; jn < 4; jn++) {
            int n = n0 + wn * 32 + jn * 8 + ncol;
            float* p = out + ((size_t)m * Ldim + n) * 2;
            *(float4*)p = make_float4(accR[im][jn][0] * INV_WSCALE,
                                      accI[im][jn][0] * INV_WSCALE,
                                      accR[im][jn][1] * INV_WSCALE,
                                      accI[im][jn][1] * INV_WSCALE);
            *(float4*)(p + (size_t)16 * Ldim) = make_float4(
                                      accR[im][jn][2] * INV_WSCALE,
                                      accI[im][jn][2] * INV_WSCALE,
                                      accR[im][jn][3] * INV_WSCALE,
                                      accI[im][jn][3] * INV_WSCALE);
        }
    }
}

// ---------------------------------------------------------------------------
extern "C" void kernel_launch(void* const* d_in, const int* in_sizes, int n_in,
                              void* d_out, int out_size) {
    const float* A = (const float*)d_in[0];
    const float* B = (const float*)d_in[1];
    const float* C = (const float*)d_in[2];

    cudaFuncSetAttribute(k_gemm, cudaFuncAttributeMaxDynamicSharedMemorySize, 163840);

    k_pre<<<4, 256>>>(A);
    k_fill<<<1536, 256>>>(B, C);
    k_gemm<<<dim3(2, 128), 512, 163840>>>((float*)d_out);
}